// round 2
// baseline (speedup 1.0000x reference)
#include <cuda_runtime.h>
#include <math.h>

#define BQ      256      // batch (queries)
#define D       512      // embedding dim
#define NTRAIN  50000    // train rows
#define NATTR   8        // attributes
#define CAP     1024     // per-b matched-sim buffer capacity (mean ~130, Binomial tail safe)
#define KNB     5        // top-k

// ---------------- device scratch (no allocations allowed) ----------------
__device__ float        g_znorm[BQ * D];     // normalized queries
__device__ unsigned int g_ptgt[BQ];          // packed target attrs (16 bits used)
__device__ int          g_count[BQ];         // matched count per query
__device__ float        g_sims[BQ * CAP];    // matched sims per query
__device__ float        g_loss[BQ];          // per-query loss contribution

// ---------------- kernel A: normalize z, pack targets, zero counts ----------------
__global__ void __launch_bounds__(128) prep_kernel(const float* __restrict__ z,
                                                   const int* __restrict__ tattr) {
    int b = blockIdx.x;
    int t = threadIdx.x;                 // 0..127, 4 floats each
    float4 v = ((const float4*)(z + (size_t)b * D))[t];
    float ss = v.x * v.x + v.y * v.y + v.z * v.z + v.w * v.w;
    #pragma unroll
    for (int o = 16; o; o >>= 1) ss += __shfl_xor_sync(0xffffffffu, ss, o);
    __shared__ float ws[4];
    if ((t & 31) == 0) ws[t >> 5] = ss;
    __syncthreads();
    float tot = ws[0] + ws[1] + ws[2] + ws[3];
    float inv = 1.0f / fmaxf(sqrtf(tot), 1e-12f);   // matches F.normalize eps semantics
    float4 o4 = make_float4(v.x * inv, v.y * inv, v.z * inv, v.w * inv);
    ((float4*)(g_znorm + (size_t)b * D))[t] = o4;
    if (t == 0) {
        g_count[b] = 0;
        unsigned p = 0;
        #pragma unroll
        for (int a = 0; a < NATTR; a++)
            p |= ((unsigned)tattr[b * NATTR + a] & 3u) << (2 * a);
        g_ptgt[b] = p;
    }
}

// ---------------- kernel B: attr match + sparse dots ----------------
// One warp per train row; 8 warps (256 threads) per block.
__global__ void __launch_bounds__(256) match_kernel(const float* __restrict__ emb,
                                                    const int* __restrict__ attr) {
    __shared__ unsigned       s_ptgt[BQ];
    __shared__ unsigned short s_list[8][BQ];
    __shared__ int            s_cnt[8];

    int t = threadIdx.x;
    int w = t >> 5, lane = t & 31;
    for (int i = t; i < BQ; i += 256) s_ptgt[i] = g_ptgt[i];
    if (lane == 0) s_cnt[w] = 0;
    __syncthreads();

    int n = blockIdx.x * 8 + w;
    if (n < NTRAIN) {
        // pack this row's attrs (lanes 0..7 each contribute one 2-bit field, OR-reduce)
        unsigned p = 0;
        if (lane < NATTR) p = ((unsigned)attr[(size_t)n * NATTR + lane] & 3u) << (2 * lane);
        #pragma unroll
        for (int o = 16; o; o >>= 1) p |= __shfl_xor_sync(0xffffffffu, p, o);

        // test against all 256 targets: mismatch count <= 1  <=>  match_score >= 7
        #pragma unroll
        for (int g = 0; g < BQ; g += 32) {
            unsigned x = p ^ s_ptgt[g + lane];
            unsigned y = (x | (x >> 1)) & 0x55555555u;
            if (__popc(y) <= 1) {
                int pos = atomicAdd(&s_cnt[w], 1);
                s_list[w][pos] = (unsigned short)(g + lane);
            }
        }
    }
    __syncwarp();
    int nm = (n < NTRAIN) ? s_cnt[w] : 0;

    if (nm > 0) {
        const float4* row = (const float4*)(emb + (size_t)n * D);
        float4 r0 = row[lane];
        float4 r1 = row[lane + 32];
        float4 r2 = row[lane + 64];
        float4 r3 = row[lane + 96];
        float ss = r0.x*r0.x + r0.y*r0.y + r0.z*r0.z + r0.w*r0.w
                 + r1.x*r1.x + r1.y*r1.y + r1.z*r1.z + r1.w*r1.w
                 + r2.x*r2.x + r2.y*r2.y + r2.z*r2.z + r2.w*r2.w
                 + r3.x*r3.x + r3.y*r3.y + r3.z*r3.z + r3.w*r3.w;
        #pragma unroll
        for (int o = 16; o; o >>= 1) ss += __shfl_xor_sync(0xffffffffu, ss, o);
        float inv = 1.0f / fmaxf(sqrtf(ss), 1e-12f);

        for (int j = 0; j < nm; j++) {
            int b = s_list[w][j];
            const float4* zr = (const float4*)(g_znorm + (size_t)b * D);
            float4 z0 = zr[lane];
            float4 z1 = zr[lane + 32];
            float4 z2 = zr[lane + 64];
            float4 z3 = zr[lane + 96];
            float d = r0.x*z0.x + r0.y*z0.y + r0.z*z0.z + r0.w*z0.w
                    + r1.x*z1.x + r1.y*z1.y + r1.z*z1.z + r1.w*z1.w
                    + r2.x*z2.x + r2.y*z2.y + r2.z*z2.z + r2.w*z2.w
                    + r3.x*z3.x + r3.y*z3.y + r3.z*z3.z + r3.w*z3.w;
            #pragma unroll
            for (int o = 16; o; o >>= 1) d += __shfl_xor_sync(0xffffffffu, d, o);
            if (lane == 0) {
                int pos = atomicAdd(&g_count[b], 1);
                if (pos < CAP) g_sims[(size_t)b * CAP + pos] = d * inv;
            }
        }
    }
}

// ---------------- kernel C: top-5 (with implicit zero padding) + per-b loss ----------------
__global__ void __launch_bounds__(32) topk_kernel() {
    __shared__ float sv[CAP];
    int b = blockIdx.x;
    int lane = threadIdx.x;
    int cnt = g_count[b];
    if (cnt > CAP) cnt = CAP;
    for (int i = lane; i < cnt; i += 32) sv[i] = g_sims[(size_t)b * CAP + i];
    __syncwarp();

    float sum5 = 0.0f;
    #pragma unroll
    for (int k = 0; k < KNB; k++) {
        float mx = -1e30f; int mi = -1;
        for (int i = lane; i < cnt; i += 32) {
            float v = sv[i];
            if (v > mx) { mx = v; mi = i; }
        }
        float bmx = mx;
        #pragma unroll
        for (int o = 16; o; o >>= 1) bmx = fmaxf(bmx, __shfl_xor_sync(0xffffffffu, bmx, o));
        // a 0 always available in masked_sim's 49k+ zeros: clamp each selection at 0
        sum5 += fmaxf(bmx, 0.0f);
        unsigned has = __ballot_sync(0xffffffffu, (mx == bmx) && (mi >= 0));
        int owner = (int)__ffs(has) - 1;
        if (lane == owner) sv[mi] = -1e30f;   // remove exactly one instance
        __syncwarp();
    }
    if (lane == 0) {
        float per = 1.0f - sum5 / (float)KNB;
        g_loss[b] = (cnt >= KNB) ? per : 0.0f;
    }
}

// ---------------- kernel D: deterministic final reduction ----------------
__global__ void __launch_bounds__(256) reduce_kernel(float* __restrict__ out) {
    __shared__ float sm[8];
    int t = threadIdx.x;
    float v = g_loss[t];
    #pragma unroll
    for (int o = 16; o; o >>= 1) v += __shfl_xor_sync(0xffffffffu, v, o);
    if ((t & 31) == 0) sm[t >> 5] = v;
    __syncthreads();
    if (t == 0) {
        float s = 0.0f;
        #pragma unroll
        for (int i = 0; i < 8; i++) s += sm[i];
        out[0] = s / (float)BQ;
    }
}

extern "C" void kernel_launch(void* const* d_in, const int* in_sizes, int n_in,
                              void* d_out, int out_size) {
    const float* z      = (const float*)d_in[0];   // z_flowed        [256,512] f32
    const int*   tattr  = (const int*)d_in[1];     // target_attrs    [256,8]   i32
    const float* emb    = (const float*)d_in[2];   // train_embeddings[50000,512] f32
    const int*   attr   = (const int*)d_in[3];     // train_attributes[50000,8] i32
    float*       out    = (float*)d_out;

    prep_kernel<<<BQ, 128>>>(z, tattr);
    match_kernel<<<(NTRAIN + 7) / 8, 256>>>(emb, attr);
    topk_kernel<<<BQ, 32>>>();
    reduce_kernel<<<1, 256>>>(out);
}